// round 1
// baseline (speedup 1.0000x reference)
#include <cuda_runtime.h>
#include <math.h>

#define N_BINS 1024
#define NMASK  (N_BINS - 1)
#define DIM    512
#define DIM4   128          // DIM / 4 (float4 units)
#define NSTEPS 240
#define NK     122          // k in [-61, 60]
#define TI     8            // bins per block in kernel A
#define WIN    (TI + NK - 1)  // 129 Q rows per block window

// Scratch (no allocations allowed; device globals are the sanctioned path)
__device__ float g_P2[N_BINS];
__device__ float g_Q2[N_BINS];
__device__ float g_A[N_BINS];
__device__ float g_part[NSTEPS * N_BINS];
__device__ float g_dist[NSTEPS];

__device__ __forceinline__ float dot4(float4 a, float4 b) {
    return a.x * b.x + a.y * b.y + a.z * b.z + a.w * b.w;
}

// ---------------------------------------------------------------------------
// Kernel 0: per-row stats.  Q2[j] = |Q[j]|^2,  A[j] = Q[j].Q[j-1],  P2[j] = |P[j]|^2
// ---------------------------------------------------------------------------
__global__ void k_rowstats(const float* __restrict__ Dq, const float* __restrict__ Dp) {
    int j = blockIdx.x;
    int tid = threadIdx.x;  // 128 threads
    const float4* q  = (const float4*)Dq + j * DIM4;
    const float4* qm = (const float4*)Dq + ((j - 1) & NMASK) * DIM4;
    const float4* p  = (const float4*)Dp + j * DIM4;
    float s_q2 = 0.f, s_a = 0.f, s_p2 = 0.f;
    for (int c = tid; c < DIM4; c += 128) {
        float4 qv = q[c], qmv = qm[c], pv = p[c];
        s_q2 += dot4(qv, qv);
        s_a  += dot4(qv, qmv);
        s_p2 += dot4(pv, pv);
    }
    #pragma unroll
    for (int off = 16; off; off >>= 1) {
        s_q2 += __shfl_xor_sync(0xffffffffu, s_q2, off);
        s_a  += __shfl_xor_sync(0xffffffffu, s_a,  off);
        s_p2 += __shfl_xor_sync(0xffffffffu, s_p2, off);
    }
    __shared__ float r[3][4];
    int w = tid >> 5, l = tid & 31;
    if (l == 0) { r[0][w] = s_q2; r[1][w] = s_a; r[2][w] = s_p2; }
    __syncthreads();
    if (tid == 0) g_Q2[j] = r[0][0] + r[0][1] + r[0][2] + r[0][3];
    if (tid == 1) g_A[j]  = r[1][0] + r[1][1] + r[1][2] + r[1][3];
    if (tid == 2) g_P2[j] = r[2][0] + r[2][1] + r[2][2] + r[2][3];
}

// ---------------------------------------------------------------------------
// Kernel A: banded cross-correlation X[i,k] = P[i] . Q[(i-k) mod N] for
// k in [-61,60], for an 8-bin tile, then evaluate all 240 steps and write
// sqrt(r2) partials.
// ---------------------------------------------------------------------------
__global__ void __launch_bounds__(256) k_xcorr(const float* __restrict__ Dq,
                                               const float* __restrict__ Dp) {
    __shared__ float4 Ps[TI][DIM4];  // 16 KB: the 8 D_p rows of this tile
    __shared__ float  Xs[TI][128];   // X indexed by (k + 61) in [0,121]

    const int i0   = blockIdx.x * TI;
    const int tid  = threadIdx.x;
    const int warp = tid >> 5;
    const int lane = tid & 31;

    const float4* P4 = (const float4*)Dp;
    const float4* Q4 = (const float4*)Dq;

    // Load 8 P rows into shared (coalesced float4)
    for (int idx = tid; idx < TI * DIM4; idx += 256) {
        int t = idx >> 7, c = idx & 127;
        Ps[t][c] = P4[(i0 + t) * DIM4 + c];
    }
    __syncthreads();

    // Stream the 129-row Q window; each warp owns rows r = warp, warp+8, ...
    for (int r = warp; r < WIN; r += 8) {
        int j = (i0 - 60 + r) & NMASK;
        const float4* q = Q4 + j * DIM4;
        float4 q0 = q[lane], q1 = q[lane + 32], q2 = q[lane + 64], q3 = q[lane + 96];
        float acc[TI];
        #pragma unroll
        for (int t = 0; t < TI; t++) {
            acc[t] = dot4(q0, Ps[t][lane])      + dot4(q1, Ps[t][lane + 32])
                   + dot4(q2, Ps[t][lane + 64]) + dot4(q3, Ps[t][lane + 96]);
        }
        #pragma unroll
        for (int t = 0; t < TI; t++) {
            float v = acc[t];
            #pragma unroll
            for (int off = 16; off; off >>= 1) v += __shfl_xor_sync(0xffffffffu, v, off);
            if (lane == 0) {
                int kk = t + 121 - r;  // = k + 61, where k = i - j = t + 60 - r
                if (kk >= 0 && kk < NK) Xs[t][kk] = v;
            }
        }
    }
    __syncthreads();

    // Evaluate all 240 steps for the 8 bins of this tile.
    for (int task = tid; task < NSTEPS * TI; task += 256) {
        int s = task % NSTEPS;
        int t = task / NSTEPS;
        int i = i0 + t;
        int k0, k1; float alpha; bool pos;
        if (s < 120) {                         // steps 0.0, 0.5, ..., 59.5
            k0 = s >> 1; k1 = k0 + 1;
            alpha = (s & 1) ? 0.5f : 0.0f;
            pos = true;
        } else {                               // steps -1.0, -1.5, ..., -60.5
            int u = s - 120;
            k0 = -(1 + (u >> 1)); k1 = k0 - 1;
            alpha = (u & 1) ? 0.5f : 0.0f;
            pos = false;
        }
        float w0 = 1.0f - alpha, w1 = alpha;
        int j0 = (i - k0) & NMASK;
        int j1 = (i - k1) & NMASK;
        // Q0.Q1 for adjacent rolls: A[j] = Q[j].Q[j-1]
        float adot = pos ? g_A[j0] : g_A[j1];
        float x0 = Xs[t][k0 + 61];
        float x1 = Xs[t][k1 + 61];
        float r2 = g_P2[i] + w0 * w0 * g_Q2[j0] + w1 * w1 * g_Q2[j1]
                 + 2.0f * w0 * w1 * adot - 2.0f * (w0 * x0 + w1 * x1);
        g_part[s * N_BINS + i] = sqrtf(fmaxf(r2, 0.0f));
    }
}

// ---------------------------------------------------------------------------
// Kernel B: dist[s] = mean_i sqrt(r2[s,i])
// ---------------------------------------------------------------------------
__global__ void k_reduce() {
    int s = blockIdx.x, tid = threadIdx.x;  // 256 threads
    float sum = 0.f;
    for (int i = tid; i < N_BINS; i += 256) sum += g_part[s * N_BINS + i];
    #pragma unroll
    for (int off = 16; off; off >>= 1) sum += __shfl_xor_sync(0xffffffffu, sum, off);
    __shared__ float r[8];
    if ((tid & 31) == 0) r[tid >> 5] = sum;
    __syncthreads();
    if (tid == 0) {
        float tot = 0.f;
        #pragma unroll
        for (int w = 0; w < 8; w++) tot += r[w];
        g_dist[s] = tot * (1.0f / N_BINS);
    }
}

// ---------------------------------------------------------------------------
// Kernel C: argmin with first-index tie-break (matches jnp.argmin), emit result
// ---------------------------------------------------------------------------
__global__ void k_argmin(float* __restrict__ out) {
    __shared__ float vals[NSTEPS];
    int tid = threadIdx.x;  // 256 threads
    if (tid < NSTEPS) vals[tid] = g_dist[tid];
    __syncthreads();
    if (tid == 0) {
        float best = vals[0]; int bi = 0;
        for (int s = 1; s < NSTEPS; s++) {
            if (vals[s] < best) { best = vals[s]; bi = s; }
        }
        float step = (bi < 120) ? 0.5f * (float)bi : -(1.0f + 0.5f * (float)(bi - 120));
        out[0] = step;
        out[1] = best;
    }
}

extern "C" void kernel_launch(void* const* d_in, const int* in_sizes, int n_in,
                              void* d_out, int out_size) {
    const float* Dq = (const float*)d_in[0];  // D_q [1024, 512]
    const float* Dp = (const float*)d_in[1];  // D_p [1024, 512]
    float* out = (float*)d_out;

    k_rowstats<<<N_BINS, 128>>>(Dq, Dp);
    k_xcorr<<<N_BINS / TI, 256>>>(Dq, Dp);
    k_reduce<<<NSTEPS, 256>>>();
    k_argmin<<<1, 256>>>(out);
}